// round 16
// baseline (speedup 1.0000x reference)
#include <cuda_runtime.h>
#include <cuda_fp16.h>
#include <cstdint>
#include <math.h>

#define B_   8
#define S_   2048
#define MD   1024
#define DK   128
#define NROWS (B_*S_)

// pre-split half2-packed projections (u32 = half2), 4.19 MB each
__device__ uint32_t g_qh[NROWS*64];            // Q hi, half2 along dk
__device__ uint32_t g_kh[NROWS*64];            // K hi, half2 along dk
__device__ uint32_t g_kl[NROWS*64];            // K lo
__device__ uint32_t g_vth[(NROWS/2)*128];      // V^T hi: [b][dk][seq half2]
__device__ uint32_t g_vtl[(NROWS/2)*128];      // V^T lo
// pre-split weights: [3][128][512] u32 (half2 along k)
__device__ uint32_t g_wh[3*128*512];
__device__ uint32_t g_wl[3*128*512];

// ===================== mma / split / cp.async / ldmatrix helpers ==================
__device__ __forceinline__ void mma_f16(float c[4],
                                        uint32_t a0, uint32_t a1, uint32_t a2, uint32_t a3,
                                        uint32_t b0, uint32_t b1)
{
    asm volatile("mma.sync.aligned.m16n8k16.row.col.f32.f16.f16.f32 "
                 "{%0,%1,%2,%3}, {%4,%5,%6,%7}, {%8,%9}, {%0,%1,%2,%3};"
                 : "+f"(c[0]), "+f"(c[1]), "+f"(c[2]), "+f"(c[3])
                 : "r"(a0), "r"(a1), "r"(a2), "r"(a3), "r"(b0), "r"(b1));
}

__device__ __forceinline__ void ldsm4(uint32_t r[4], uint32_t saddr) {
    asm volatile("ldmatrix.sync.aligned.m8n8.x4.shared.b16 {%0,%1,%2,%3}, [%4];"
                 : "=r"(r[0]), "=r"(r[1]), "=r"(r[2]), "=r"(r[3]) : "r"(saddr));
}

__device__ __forceinline__ void split2h(float x0, float x1, uint32_t& hi, uint32_t& lo) {
    __half2 h = __floats2half2_rn(x0, x1);
    float2 f = __half22float2(h);
    __half2 l = __floats2half2_rn(x0 - f.x, x1 - f.y);
    hi = *reinterpret_cast<uint32_t*>(&h);
    lo = *reinterpret_cast<uint32_t*>(&l);
}

__device__ __forceinline__ uint32_t pack2h(float x0, float x1) {
    __half2 h = __floats2half2_rn(x0, x1);
    return *reinterpret_cast<uint32_t*>(&h);
}

__device__ __forceinline__ void cp_async16(uint32_t* smem_dst, const void* gsrc) {
    uint32_t s = (uint32_t)__cvta_generic_to_shared(smem_dst);
    asm volatile("cp.async.cg.shared.global [%0], [%1], 16;" :: "r"(s), "l"(gsrc) : "memory");
}
#define CP_COMMIT() asm volatile("cp.async.commit_group;" ::: "memory")
#define CP_WAIT(n)  asm volatile("cp.async.wait_group %0;" :: "n"(n) : "memory")

__device__ __forceinline__ void prefetch_l2(const void* p) {
    asm volatile("prefetch.global.L2 [%0];" :: "l"(p));
}

// ===================== W pre-split kernel =====================
__global__ __launch_bounds__(256) void presplit_w(
    const float* __restrict__ Wq, const float* __restrict__ Wk, const float* __restrict__ Wv)
{
    int idx = blockIdx.x * 256 + threadIdx.x;
    int w = idx >> 16;
    int rem = idx & 65535;
    const float* W = (w == 0) ? Wq : (w == 1) ? Wk : Wv;
    float2 v = *(const float2*)(W + rem * 2);
    uint32_t h, l;
    split2h(v.x, v.y, h, l);
    g_wh[idx] = h;
    g_wl[idx] = l;
}

// ===================== projection: fp16 3-term split, reg double-buffer ===========
#define PJ_S  36
#define PJ_AH 0
#define PJ_AL 4608
#define PJ_BH 9216
#define PJ_BL 13824
#define PJ_SMEM_BYTES (18432 * 4)

__global__ __launch_bounds__(512) void proj_mma(
    const float* __restrict__ Xq, const float* __restrict__ Xk, const float* __restrict__ Xv)
{
    const int kind = blockIdx.y;                    // 0=Q 1=K 2=V
    const float* X = (kind == 0) ? Xq : (kind == 1) ? Xk : Xv;

    extern __shared__ uint32_t su[];
    const uint32_t sb4 = (uint32_t)__cvta_generic_to_shared(su);

    const int tid  = threadIdx.x;
    const int wid  = tid >> 5, lane = tid & 31;
    const int wr   = wid >> 2, wc = wid & 3;
    const int rowt = lane >> 2;
    const int colt = lane & 3;
    const int row0 = blockIdx.x * 128;
    const uint4* Wh4 = (const uint4*)(g_wh + kind * 65536);
    const uint4* Wl4 = (const uint4*)(g_wl + kind * 65536);

    const int lrow = lane & 7, lsel = lane >> 3;
    const int aoff = ((lsel & 1) * 8 + lrow) * PJ_S + (lsel >> 1) * 4;
    const int boff = ((lsel >> 1) * 8 + lrow) * PJ_S + (lsel & 1) * 4;

    // per-thread staging indices
    const int a_row = tid >> 2, a_f4 = tid & 3;      // 4 rows span: rows tid>>2, +128? no: 512 thr, 4 iters
    // A: idx = tid + t*512, row = idx>>4, f4 = idx&15
    // W: idx = tid + t*512, row = idx>>3, c4 = idx&7
    (void)a_row; (void)a_f4;

    float acc[2][4][4];
    #pragma unroll
    for (int mt = 0; mt < 2; mt++)
        #pragma unroll
        for (int nt = 0; nt < 4; nt++)
            #pragma unroll
            for (int i = 0; i < 4; i++) acc[mt][nt][i] = 0.f;

    // ---- prologue: load stage 0 into regs ----
    float4 xr[4];
    uint4  whr[2], wlr[2];
    #pragma unroll
    for (int t = 0; t < 4; t++) {
        int idx = tid + t * 512;
        int row = idx >> 4, f4 = idx & 15;
        xr[t] = *(const float4*)(X + (size_t)(row0 + row) * MD + 0 + f4 * 4);
    }
    #pragma unroll
    for (int t = 0; t < 2; t++) {
        int idx = tid + t * 512;
        int row = idx >> 3, c4 = idx & 7;
        int g = row * 128 + 0 + c4;
        whr[t] = Wh4[g];
        wlr[t] = Wl4[g];
    }

    #pragma unroll 1
    for (int s = 0; s < 16; s++) {
        // ---- store staged regs to smem (split X in regs) ----
        #pragma unroll
        for (int t = 0; t < 4; t++) {
            int idx = tid + t * 512;
            int row = idx >> 4, f4 = idx & 15;
            uint32_t h0, l0, h1, l1;
            split2h(xr[t].x, xr[t].y, h0, l0);
            split2h(xr[t].z, xr[t].w, h1, l1);
            *(uint2*)&su[PJ_AH + row * PJ_S + f4 * 2] = make_uint2(h0, h1);
            *(uint2*)&su[PJ_AL + row * PJ_S + f4 * 2] = make_uint2(l0, l1);
        }
        #pragma unroll
        for (int t = 0; t < 2; t++) {
            int idx = tid + t * 512;
            int row = idx >> 3, c4 = idx & 7;
            *(uint4*)&su[PJ_BH + row * PJ_S + c4 * 4] = whr[t];
            *(uint4*)&su[PJ_BL + row * PJ_S + c4 * 4] = wlr[t];
        }
        __syncthreads();

        // ---- prefetch next stage into regs (overlaps MMAs below) ----
        if (s < 15) {
            int k0n = (s + 1) * 64;
            #pragma unroll
            for (int t = 0; t < 4; t++) {
                int idx = tid + t * 512;
                int row = idx >> 4, f4 = idx & 15;
                xr[t] = *(const float4*)(X + (size_t)(row0 + row) * MD + k0n + f4 * 4);
            }
            #pragma unroll
            for (int t = 0; t < 2; t++) {
                int idx = tid + t * 512;
                int row = idx >> 3, c4 = idx & 7;
                int g = row * 128 + (k0n >> 3) + c4;
                whr[t] = Wh4[g];
                wlr[t] = Wl4[g];
            }
        }

        // ---- MMAs on staged tile ----
        #pragma unroll
        for (int c = 0; c < 4; c++) {
            const int co = c * 8;
            uint32_t ah[2][4], al[2][4];
            #pragma unroll
            for (int mt = 0; mt < 2; mt++) {
                int base = (wr * 32 + mt * 16) * PJ_S + aoff + co;
                ldsm4(ah[mt], sb4 + 4 * (PJ_AH + base));
                ldsm4(al[mt], sb4 + 4 * (PJ_AL + base));
            }
            uint32_t bh[2][4], bl[2][4];
            #pragma unroll
            for (int p = 0; p < 2; p++) {
                int base = (wc * 32 + p * 16) * PJ_S + boff + co;
                ldsm4(bh[p], sb4 + 4 * (PJ_BH + base));
                ldsm4(bl[p], sb4 + 4 * (PJ_BL + base));
            }
            #pragma unroll
            for (int p = 0; p < 2; p++)
                #pragma unroll
                for (int q = 0; q < 2; q++) {
                    int nt = 2 * p + q;
                    uint32_t b0 = bh[p][2*q], b1 = bh[p][2*q+1];
                    uint32_t l0 = bl[p][2*q], l1 = bl[p][2*q+1];
                    #pragma unroll
                    for (int mt = 0; mt < 2; mt++) {
                        mma_f16(acc[mt][nt], ah[mt][0], ah[mt][1], ah[mt][2], ah[mt][3], b0, b1);
                        mma_f16(acc[mt][nt], ah[mt][0], ah[mt][1], ah[mt][2], ah[mt][3], l0, l1);
                        mma_f16(acc[mt][nt], al[mt][0], al[mt][1], al[mt][2], al[mt][3], b0, b1);
                    }
                }
        }
        __syncthreads();
    }

    // ---- epilogue ----
    if (kind == 2) {
        #pragma unroll
        for (int mt = 0; mt < 2; mt++) {
            int gr = row0 + wr * 32 + mt * 16 + rowt;
            #pragma unroll
            for (int nt = 0; nt < 4; nt++) {
                int gc = wc * 32 + nt * 8 + colt * 2;
                float o0 = __shfl_xor_sync(0xffffffffu, acc[mt][nt][0], 4);
                float o1 = __shfl_xor_sync(0xffffffffu, acc[mt][nt][1], 4);
                float o2 = __shfl_xor_sync(0xffffffffu, acc[mt][nt][2], 4);
                float o3 = __shfl_xor_sync(0xffffffffu, acc[mt][nt][3], 4);
                if ((rowt & 1) == 0) {
                    int bb = gr >> 11;
                    int s0 = (gr & 2047) >> 1;
                    int s1 = ((gr + 8) & 2047) >> 1;
                    uint32_t h, l;
                    split2h(acc[mt][nt][0], o0, h, l);
                    g_vth[((bb * 128 + gc) << 10) + s0] = h;
                    g_vtl[((bb * 128 + gc) << 10) + s0] = l;
                    split2h(acc[mt][nt][1], o1, h, l);
                    g_vth[((bb * 128 + gc + 1) << 10) + s0] = h;
                    g_vtl[((bb * 128 + gc + 1) << 10) + s0] = l;
                    split2h(acc[mt][nt][2], o2, h, l);
                    g_vth[((bb * 128 + gc) << 10) + s1] = h;
                    g_vtl[((bb * 128 + gc) << 10) + s1] = l;
                    split2h(acc[mt][nt][3], o3, h, l);
                    g_vth[((bb * 128 + gc + 1) << 10) + s1] = h;
                    g_vtl[((bb * 128 + gc + 1) << 10) + s1] = l;
                }
            }
        }
    } else {
        #pragma unroll
        for (int mt = 0; mt < 2; mt++) {
            int gr = row0 + wr * 32 + mt * 16 + rowt;
            #pragma unroll
            for (int nt = 0; nt < 4; nt++) {
                int gc = wc * 32 + nt * 8 + colt * 2;
                int o0 = gr * 64 + (gc >> 1);
                int o1 = (gr + 8) * 64 + (gc >> 1);
                if (kind == 0) {
                    g_qh[o0] = pack2h(acc[mt][nt][0], acc[mt][nt][1]);
                    g_qh[o1] = pack2h(acc[mt][nt][2], acc[mt][nt][3]);
                } else {
                    uint32_t h, l;
                    split2h(acc[mt][nt][0], acc[mt][nt][1], h, l);
                    g_kh[o0] = h;  g_kl[o0] = l;
                    split2h(acc[mt][nt][2], acc[mt][nt][3], h, l);
                    g_kh[o1] = h;  g_kl[o1] = l;
                }
            }
        }
    }
}

// ===================== fp16 flash attention, BQ=128, 512 thr ======================
#define AQ_S  68
#define U_Q   0                       // Qh: 8704 u32
#define U_K   8704                    // Kh @+0, Kl @+8704     (17408 u32)
#define U_V   26112                   // Vh @+0, Vl @+8704     (17408 u32)
#define U_P   43520                   // Ph: 8704
#define U_RM  52224                   // redmax: 128 x 4
#define U_RS  52736                   // redsum: 128 x 4
#define A_SMEM_BYTES ((53248) * 4)    // 212,992 B

__global__ __launch_bounds__(512) void attn_tc(const int* __restrict__ mask,
                                               float* __restrict__ out)
{
    extern __shared__ uint32_t su[];
    const uint32_t sb4 = (uint32_t)__cvta_generic_to_shared(su);
    float* redm = (float*)&su[U_RM];
    float* reds = (float*)&su[U_RS];

    const int tid = threadIdx.x;
    const int wid = tid >> 5, lane = tid & 31;
    const int wr = wid >> 2, wc = wid & 3;
    const int rowt = lane >> 2, colt = lane & 3;
    const int qt = blockIdx.x, b = blockIdx.y;

    const int lrow = lane & 7, lsel = lane >> 3;
    const int aoff = ((lsel & 1) * 8 + lrow) * AQ_S + (lsel >> 1) * 4;
    const int boff = ((lsel >> 1) * 8 + lrow) * AQ_S + (lsel & 1) * 4;

    const uint4* Qg   = (const uint4*)(g_qh + ((size_t)b * S_ + (size_t)qt * 128) * 64);
    const uint4* Khg0 = (const uint4*)(g_kh + (size_t)b * S_ * 64);
    const uint4* Klg0 = (const uint4*)(g_kl + (size_t)b * S_ * 64);
    const uint4* Vhg0 = (const uint4*)(g_vth) + (size_t)b * 32768;
    const uint4* Vlg0 = (const uint4*)(g_vtl) + (size_t)b * 32768;

    // mask prefetch address: one 128B line per thread covers the 64KB tile
    const int* mpre_base = mask + ((size_t)b * S_ + (size_t)qt * 128 + (tid >> 2)) * S_
                                + (tid & 3) * 32;

    // ---- stage Q (copy) ----
    #pragma unroll
    for (int t = 0; t < 4; t++) {
        int idx = tid + t * 512;
        int row = idx >> 4, c4 = idx & 15;
        *(uint4*)&su[U_Q + row * AQ_S + c4 * 4] = Qg[idx];
    }

    // ---- prologue: issue K[0], V[0]; prefetch mask[0] ----
    {
        #pragma unroll
        for (int t = 0; t < 4; t++) {
            int idx = tid + t * 512;
            int row = idx >> 4, c4 = idx & 15;
            cp_async16(&su[U_K + row * AQ_S + c4 * 4],        Khg0 + idx);
            cp_async16(&su[U_K + 8704 + row * AQ_S + c4 * 4], Klg0 + idx);
        }
        CP_COMMIT();
        #pragma unroll
        for (int t = 0; t < 4; t++) {
            int idx = tid + t * 512;
            int row = idx >> 4, c4 = idx & 15;
            cp_async16(&su[U_V + row * AQ_S + c4 * 4],        Vhg0 + row * 256 + c4);
            cp_async16(&su[U_V + 8704 + row * AQ_S + c4 * 4], Vlg0 + row * 256 + c4);
        }
        CP_COMMIT();
        prefetch_l2(mpre_base);
    }

    float acc[2][4][4];
    #pragma unroll
    for (int mt = 0; mt < 2; mt++)
        #pragma unroll
        for (int nt = 0; nt < 4; nt++)
            #pragma unroll
            for (int i = 0; i < 4; i++) acc[mt][nt][i] = 0.f;

    float mrow[4] = {-1e30f, -1e30f, -1e30f, -1e30f};
    float lrowv[4] = {0.f, 0.f, 0.f, 0.f};
    const float scale = 0.08838834764831845f;

    #pragma unroll 1
    for (int kt = 0; kt < S_ / 128; kt++) {
        CP_WAIT(1);                 // K[kt] landed
        __syncthreads();

        // ---- prefetch mask[kt+1] to L2 (covers next iteration) ----
        if (kt + 1 < S_ / 128)
            prefetch_l2(mpre_base + (size_t)(kt + 1) * 128);

        // ---- S = Qh*(Kh+Kl), ldmatrix operands ----
        float s[2][4][4];
        #pragma unroll
        for (int mt = 0; mt < 2; mt++)
            #pragma unroll
            for (int nt = 0; nt < 4; nt++)
                #pragma unroll
                for (int i = 0; i < 4; i++) s[mt][nt][i] = 0.f;

        #pragma unroll 1
        for (int c = 0; c < 8; c++) {
            const int co = c * 8;
            uint32_t ah[2][4];
            #pragma unroll
            for (int mt = 0; mt < 2; mt++)
                ldsm4(ah[mt], sb4 + 4 * (U_Q + (wr * 32 + mt * 16) * AQ_S + aoff + co));
            uint32_t kh[2][4], kl[2][4];
            #pragma unroll
            for (int p = 0; p < 2; p++) {
                int base = (wc * 32 + p * 16) * AQ_S + boff + co;
                ldsm4(kh[p], sb4 + 4 * (U_K + base));
                ldsm4(kl[p], sb4 + 4 * (U_K + 8704 + base));
            }
            #pragma unroll
            for (int p = 0; p < 2; p++)
                #pragma unroll
                for (int q = 0; q < 2; q++) {
                    int nt = 2 * p + q;
                    #pragma unroll
                    for (int mt = 0; mt < 2; mt++) {
                        mma_f16(s[mt][nt], ah[mt][0], ah[mt][1], ah[mt][2], ah[mt][3],
                                kh[p][2*q], kh[p][2*q+1]);
                        mma_f16(s[mt][nt], ah[mt][0], ah[mt][1], ah[mt][2], ah[mt][3],
                                kl[p][2*q], kl[p][2*q+1]);
                    }
                }
        }

        // ---- mask + scale; per-warp partial row max ----
        const int* mbase = mask + ((size_t)b * S_ + (size_t)qt * 128) * S_ + (size_t)kt * 128
                                + wc * 32 + colt * 2;
        #pragma unroll
        for (int mt = 0; mt < 2; mt++) {
            int r0 = wr * 32 + mt * 16 + rowt;
            const int* m0p = mbase + (size_t)r0 * S_;
            const int* m1p = mbase + (size_t)(r0 + 8) * S_;
            float mx0 = -1e30f, mx1 = -1e30f;
            #pragma unroll
            for (int nt = 0; nt < 4; nt++) {
                int2 ma = *(const int2*)(m0p + nt * 8);
                int2 mb = *(const int2*)(m1p + nt * 8);
                s[mt][nt][0] = ma.x ? s[mt][nt][0] * scale : -1e9f;
                s[mt][nt][1] = ma.y ? s[mt][nt][1] * scale : -1e9f;
                s[mt][nt][2] = mb.x ? s[mt][nt][2] * scale : -1e9f;
                s[mt][nt][3] = mb.y ? s[mt][nt][3] * scale : -1e9f;
                mx0 = fmaxf(mx0, fmaxf(s[mt][nt][0], s[mt][nt][1]));
                mx1 = fmaxf(mx1, fmaxf(s[mt][nt][2], s[mt][nt][3]));
            }
            mx0 = fmaxf(mx0, __shfl_xor_sync(0xffffffffu, mx0, 1));
            mx0 = fmaxf(mx0, __shfl_xor_sync(0xffffffffu, mx0, 2));
            mx1 = fmaxf(mx1, __shfl_xor_sync(0xffffffffu, mx1, 1));
            mx1 = fmaxf(mx1, __shfl_xor_sync(0xffffffffu, mx1, 2));
            if (colt == 0) {
                redm[r0 * 4 + wc]       = mx0;
                redm[(r0 + 8) * 4 + wc] = mx1;
            }
        }
        __syncthreads();            // K consumed; redm visible

        // ---- prefetch K[kt+1] ----
        if (kt + 1 < S_ / 128) {
            const uint4* Khg = Khg0 + (size_t)(kt + 1) * 2048;
            const uint4* Klg = Klg0 + (size_t)(kt + 1) * 2048;
            #pragma unroll
            for (int t = 0; t < 4; t++) {
                int idx = tid + t * 512;
                int row = idx >> 4, c4 = idx & 15;
                cp_async16(&su[U_K + row * AQ_S + c4 * 4],        Khg + idx);
                cp_async16(&su[U_K + 8704 + row * AQ_S + c4 * 4], Klg + idx);
            }
            CP_COMMIT();
        }

        // ---- softmax: exp, partial sums, rescale acc, write Ph ----
        float crr[4];
        #pragma unroll
        for (int mt = 0; mt < 2; mt++) {
            int r0 = wr * 32 + mt * 16 + rowt;
            int r1 = r0 + 8;
            float mn0 = fmaxf(fmaxf(redm[r0 * 4], redm[r0 * 4 + 1]),
                              fmaxf(redm[r0 * 4 + 2], redm[r0 * 4 + 3]));
            float mn1 = fmaxf(fmaxf(redm[r1 * 4], redm[r1 * 4 + 1]),
                              fmaxf(redm[r1 * 4 + 2], redm[r1 * 4 + 3]));
            mn0 = fmaxf(mrow[mt*2], mn0);
            mn1 = fmaxf(mrow[mt*2+1], mn1);
            crr[mt*2]   = __expf(mrow[mt*2]   - mn0);
            crr[mt*2+1] = __expf(mrow[mt*2+1] - mn1);
            mrow[mt*2] = mn0;  mrow[mt*2+1] = mn1;
            float sm0 = 0.f, sm1 = 0.f;
            #pragma unroll
            for (int nt = 0; nt < 4; nt++) {
                float p0 = __expf(s[mt][nt][0] - mn0);
                float p1 = __expf(s[mt][nt][1] - mn0);
                float p2 = __expf(s[mt][nt][2] - mn1);
                float p3 = __expf(s[mt][nt][3] - mn1);
                sm0 += p0 + p1;  sm1 += p2 + p3;
                int pc = wc * 16 + nt * 4 + colt;
                su[U_P + r0 * AQ_S + pc] = pack2h(p0, p1);
                su[U_P + r1 * AQ_S + pc] = pack2h(p2, p3);
                acc[mt][nt][0] *= crr[mt*2];   acc[mt][nt][1] *= crr[mt*2];
                acc[mt][nt][2] *= crr[mt*2+1]; acc[mt][nt][3] *= crr[mt*2+1];
            }
            sm0 += __shfl_xor_sync(0xffffffffu, sm0, 1);
            sm0 += __shfl_xor_sync(0xffffffffu, sm0, 2);
            sm1 += __shfl_xor_sync(0xffffffffu, sm1, 1);
            sm1 += __shfl_xor_sync(0xffffffffu, sm1, 2);
            if (colt == 0) {
                reds[r0 * 4 + wc] = sm0;
                reds[r1 * 4 + wc] = sm1;
            }
        }

        // ---- wait V[kt], make P visible ----
        if (kt + 1 < S_ / 128) { CP_WAIT(1); } else { CP_WAIT(0); }
        __syncthreads();            // P + reds + V visible

        // ---- update l ----
        #pragma unroll
        for (int mt = 0; mt < 2; mt++) {
            int r0 = wr * 32 + mt * 16 + rowt;
            int r1 = r0 + 8;
            lrowv[mt*2]   = lrowv[mt*2]   * crr[mt*2]
                          + reds[r0*4] + reds[r0*4+1] + reds[r0*4+2] + reds[r0*4+3];
            lrowv[mt*2+1] = lrowv[mt*2+1] * crr[mt*2+1]
                          + reds[r1*4] + reds[r1*4+1] + reds[r1*4+2] + reds[r1*4+3];
        }

        // ---- acc += Ph * (Vh + Vl), ldmatrix operands ----
        #pragma unroll 1
        for (int c = 0; c < 8; c++) {
            const int co = c * 8;
            uint32_t ph[2][4];
            #pragma unroll
            for (int mt = 0; mt < 2; mt++)
                ldsm4(ph[mt], sb4 + 4 * (U_P + (wr * 32 + mt * 16) * AQ_S + aoff + co));
            uint32_t vh[2][4], vl[2][4];
            #pragma unroll
            for (int p = 0; p < 2; p++) {
                int base = (wc * 32 + p * 16) * AQ_S + boff + co;
                ldsm4(vh[p], sb4 + 4 * (U_V + base));
                ldsm4(vl[p], sb4 + 4 * (U_V + 8704 + base));
            }
            #pragma unroll
            for (int p = 0; p < 2; p++)
                #pragma unroll
                for (int q = 0; q < 2; q++) {
                    int nt = 2 * p + q;
                    #pragma unroll
                    for (int mt = 0; mt < 2; mt++) {
                        mma_f16(acc[mt][nt], ph[mt][0], ph[mt][1], ph[mt][2], ph[mt][3],
                                vh[p][2*q], vh[p][2*q+1]);
                        mma_f16(acc[mt][nt], ph[mt][0], ph[mt][1], ph[mt][2], ph[mt][3],
                                vl[p][2*q], vl[p][2*q+1]);
                    }
                }
        }
        __syncthreads();            // PV done reading V & P

        // ---- issue V[kt+1] ----
        if (kt + 1 < S_ / 128) {
            const uint4* Vhg = Vhg0 + (size_t)(kt + 1) * 16;
            const uint4* Vlg = Vlg0 + (size_t)(kt + 1) * 16;
            #pragma unroll
            for (int t = 0; t < 4; t++) {
                int idx = tid + t * 512;
                int row = idx >> 4, c4 = idx & 15;
                cp_async16(&su[U_V + row * AQ_S + c4 * 4],        Vhg + row * 256 + c4);
                cp_async16(&su[U_V + 8704 + row * AQ_S + c4 * 4], Vlg + row * 256 + c4);
            }
            CP_COMMIT();
        }
    }

    // ---- epilogue ----
    #pragma unroll
    for (int mt = 0; mt < 2; mt++) {
        int r0 = wr * 32 + mt * 16 + rowt;
        float il0 = 1.f / lrowv[mt*2];
        float il1 = 1.f / lrowv[mt*2+1];
        size_t gr = (size_t)b * S_ + (size_t)qt * 128 + r0;
        #pragma unroll
        for (int nt = 0; nt < 4; nt++) {
            int c0 = wc * 32 + nt * 8 + colt * 2;
            float2 o0 = { acc[mt][nt][0] * il0, acc[mt][nt][1] * il0 };
            float2 o1 = { acc[mt][nt][2] * il1, acc[mt][nt][3] * il1 };
            *(float2*)(out + gr * DK + c0)       = o0;
            *(float2*)(out + (gr + 8) * DK + c0) = o1;
        }
    }
}

// ===================== launch =====================
extern "C" void kernel_launch(void* const* d_in, const int* in_sizes, int n_in,
                              void* d_out, int out_size)
{
    const float* query = (const float*)d_in[0];
    const float* key   = (const float*)d_in[1];
    const float* value = (const float*)d_in[2];
    const int*   maskp = (const int*)  d_in[3];
    const float* Wq    = (const float*)d_in[4];
    const float* Wk    = (const float*)d_in[5];
    const float* Wv    = (const float*)d_in[6];
    float* out = (float*)d_out;

    cudaFuncSetAttribute(proj_mma, cudaFuncAttributeMaxDynamicSharedMemorySize,
                         (int)PJ_SMEM_BYTES);
    cudaFuncSetAttribute(attn_tc, cudaFuncAttributeMaxDynamicSharedMemorySize,
                         (int)A_SMEM_BYTES);

    presplit_w<<<768, 256>>>(Wq, Wk, Wv);
    proj_mma<<<dim3(NROWS / 128, 3), 512, PJ_SMEM_BYTES>>>(query, key, value);
    attn_tc<<<dim3(S_ / 128, B_), 512, A_SMEM_BYTES>>>(maskp, out);
}

// round 17
// speedup vs baseline: 1.4640x; 1.4640x over previous
#include <cuda_runtime.h>
#include <cuda_fp16.h>
#include <cstdint>
#include <math.h>

#define B_   8
#define S_   2048
#define MD   1024
#define DK   128
#define NROWS (B_*S_)

// half2-packed projections (u32 = half2 along dk), 4.19 MB each
__device__ uint32_t g_qh[NROWS*64];
__device__ uint32_t g_kh[NROWS*64];
__device__ uint32_t g_vh[NROWS*64];
// pre-split weights: [3][128][512] u32 (half2 along k)
__device__ uint32_t g_wh[3*128*512];
__device__ uint32_t g_wl[3*128*512];

// ===================== fp16 mma + split helpers =====================
__device__ __forceinline__ void mma_f16(float c[4],
                                        uint32_t a0, uint32_t a1, uint32_t a2, uint32_t a3,
                                        uint32_t b0, uint32_t b1)
{
    asm volatile("mma.sync.aligned.m16n8k16.row.col.f32.f16.f16.f32 "
                 "{%0,%1,%2,%3}, {%4,%5,%6,%7}, {%8,%9}, {%0,%1,%2,%3};"
                 : "+f"(c[0]), "+f"(c[1]), "+f"(c[2]), "+f"(c[3])
                 : "r"(a0), "r"(a1), "r"(a2), "r"(a3), "r"(b0), "r"(b1));
}

__device__ __forceinline__ void split2h(float x0, float x1, uint32_t& hi, uint32_t& lo) {
    __half2 h = __floats2half2_rn(x0, x1);
    float2 f = __half22float2(h);
    __half2 l = __floats2half2_rn(x0 - f.x, x1 - f.y);
    hi = *reinterpret_cast<uint32_t*>(&h);
    lo = *reinterpret_cast<uint32_t*>(&l);
}

__device__ __forceinline__ uint32_t pack2h(float x0, float x1) {
    __half2 h = __floats2half2_rn(x0, x1);
    return *reinterpret_cast<uint32_t*>(&h);
}

// ===================== W pre-split kernel =====================
__global__ __launch_bounds__(256) void presplit_w(
    const float* __restrict__ Wq, const float* __restrict__ Wk, const float* __restrict__ Wv)
{
    int idx = blockIdx.x * 256 + threadIdx.x;       // 0 .. 3*128*512-1
    int w = idx >> 16;
    int rem = idx & 65535;
    const float* W = (w == 0) ? Wq : (w == 1) ? Wk : Wv;
    float2 v = *(const float2*)(W + rem * 2);
    uint32_t h, l;
    split2h(v.x, v.y, h, l);
    g_wh[idx] = h;
    g_wl[idx] = l;
}

// ===================== projection: fp16 3-term split, 512 thr (R10 form) ==========
#define PJ_S  36
#define PJ_AH 0
#define PJ_AL 4608
#define PJ_BH 9216
#define PJ_BL 13824
#define PJ_SMEM_BYTES (18432 * 4)

__global__ __launch_bounds__(512) void proj_mma(
    const float* __restrict__ Xq, const float* __restrict__ Xk, const float* __restrict__ Xv)
{
    const int kind = blockIdx.y;                    // 0=Q 1=K 2=V
    const float* X = (kind == 0) ? Xq : (kind == 1) ? Xk : Xv;

    extern __shared__ uint32_t su[];

    const int tid  = threadIdx.x;
    const int wid  = tid >> 5, lane = tid & 31;
    const int wr   = wid >> 2, wc = wid & 3;
    const int rowt = lane >> 2;
    const int colt = lane & 3;
    const int row0 = blockIdx.x * 128;
    const uint4* Wh4 = (const uint4*)(g_wh + kind * 65536);
    const uint4* Wl4 = (const uint4*)(g_wl + kind * 65536);

    float acc[2][4][4];
    #pragma unroll
    for (int mt = 0; mt < 2; mt++)
        #pragma unroll
        for (int nt = 0; nt < 4; nt++)
            #pragma unroll
            for (int i = 0; i < 4; i++) acc[mt][nt][i] = 0.f;

    #pragma unroll 1
    for (int k0 = 0; k0 < MD; k0 += 64) {
        // ---- stage A (split X in regs) ----
        #pragma unroll
        for (int t = 0; t < 4; t++) {
            int idx = tid + t * 512;
            int row = idx >> 4, f4 = idx & 15;
            float4 a = *(const float4*)(X + (size_t)(row0 + row) * MD + k0 + f4 * 4);
            uint32_t h0, l0, h1, l1;
            split2h(a.x, a.y, h0, l0);
            split2h(a.z, a.w, h1, l1);
            *(uint2*)&su[PJ_AH + row * PJ_S + f4 * 2] = make_uint2(h0, h1);
            *(uint2*)&su[PJ_AL + row * PJ_S + f4 * 2] = make_uint2(l0, l1);
        }
        // ---- stage B (pure copy of pre-split W) ----
        #pragma unroll
        for (int t = 0; t < 2; t++) {
            int idx = tid + t * 512;
            int row = idx >> 3, c4 = idx & 7;
            int g = row * 128 + (k0 >> 3) + c4;
            *(uint4*)&su[PJ_BH + row * PJ_S + c4 * 4] = Wh4[g];
            *(uint4*)&su[PJ_BL + row * PJ_S + c4 * 4] = Wl4[g];
        }
        __syncthreads();

        #pragma unroll
        for (int c = 0; c < 4; c++) {
            const int co = c * 8;
            uint32_t ah[2][4], al[2][4];
            #pragma unroll
            for (int mt = 0; mt < 2; mt++) {
                int o0 = (wr * 32 + mt * 16 + rowt) * PJ_S + co + colt;
                int o1 = o0 + 8 * PJ_S;
                ah[mt][0] = su[PJ_AH + o0];      ah[mt][1] = su[PJ_AH + o1];
                ah[mt][2] = su[PJ_AH + o0 + 4];  ah[mt][3] = su[PJ_AH + o1 + 4];
                al[mt][0] = su[PJ_AL + o0];      al[mt][1] = su[PJ_AL + o1];
                al[mt][2] = su[PJ_AL + o0 + 4];  al[mt][3] = su[PJ_AL + o1 + 4];
            }
            #pragma unroll
            for (int nt = 0; nt < 4; nt++) {
                int ob = (wc * 32 + nt * 8 + rowt) * PJ_S + co + colt;
                uint32_t bh0 = su[PJ_BH + ob], bh1 = su[PJ_BH + ob + 4];
                uint32_t bl0 = su[PJ_BL + ob], bl1 = su[PJ_BL + ob + 4];
                #pragma unroll
                for (int mt = 0; mt < 2; mt++) {
                    mma_f16(acc[mt][nt], ah[mt][0], ah[mt][1], ah[mt][2], ah[mt][3], bh0, bh1);
                    mma_f16(acc[mt][nt], ah[mt][0], ah[mt][1], ah[mt][2], ah[mt][3], bl0, bl1);
                    mma_f16(acc[mt][nt], al[mt][0], al[mt][1], al[mt][2], al[mt][3], bh0, bh1);
                }
            }
        }
        __syncthreads();
    }

    // ---- epilogue: write packed hi-only half2 for all of q/k/v ----
    uint32_t* G = (kind == 0) ? g_qh : (kind == 1) ? g_kh : g_vh;
    #pragma unroll
    for (int mt = 0; mt < 2; mt++) {
        int gr = row0 + wr * 32 + mt * 16 + rowt;
        #pragma unroll
        for (int nt = 0; nt < 4; nt++) {
            int gc = wc * 32 + nt * 8 + colt * 2;
            G[gr * 64 + (gc >> 1)]       = pack2h(acc[mt][nt][0], acc[mt][nt][1]);
            G[(gr + 8) * 64 + (gc >> 1)] = pack2h(acc[mt][nt][2], acc[mt][nt][3]);
        }
    }
}

// ===================== fp16 flash attention, BQ=128, 512 thr, hi-only K/V =========
// 16 warps (4x4), warp tile 32x32.  QK = Qh*Kh.  PV = Ph*Vh.  128 MMAs/warp/iter.

#define AQ_S  68
#define AV_S  136
#define U_Q   0                       // Qh: 8704 u32
#define U_K   8704                    // Kh: 8704 u32
#define U_V   17408                   // Vh (transposed pack): 64*136 = 8704 u32
#define U_P   26112                   // Ph: 8704 u32
#define U_RM  34816                   // redmax: 128 x 4
#define U_RS  35328                   // redsum: 128 x 4
#define A_SMEM_BYTES ((35840) * 4)    // 143,360 B

__global__ __launch_bounds__(512) void attn_tc(const int* __restrict__ mask,
                                               float* __restrict__ out)
{
    extern __shared__ uint32_t su[];
    float* redm = (float*)&su[U_RM];
    float* reds = (float*)&su[U_RS];

    const int tid = threadIdx.x;
    const int wid = tid >> 5, lane = tid & 31;
    const int wr = wid >> 2, wc = wid & 3;
    const int rowt = lane >> 2, colt = lane & 3;
    const int qt = blockIdx.x, b = blockIdx.y;

    const uint4* Qg = (const uint4*)(g_qh + ((size_t)b * S_ + (size_t)qt * 128) * 64);

    // ---- stage Q (copy) ----
    #pragma unroll
    for (int t = 0; t < 4; t++) {
        int idx = tid + t * 512;                   // 0..2047 uint4
        int row = idx >> 4, c4 = idx & 15;
        *(uint4*)&su[U_Q + row * AQ_S + c4 * 4] = Qg[idx];
    }

    float acc[2][4][4];
    #pragma unroll
    for (int mt = 0; mt < 2; mt++)
        #pragma unroll
        for (int nt = 0; nt < 4; nt++)
            #pragma unroll
            for (int i = 0; i < 4; i++) acc[mt][nt][i] = 0.f;

    float mrow[4] = {-1e30f, -1e30f, -1e30f, -1e30f};
    float lrow[4] = {0.f, 0.f, 0.f, 0.f};
    const float scale = 0.08838834764831845f;

    #pragma unroll 1
    for (int kt = 0; kt < S_ / 128; kt++) {
        __syncthreads();
        // ---- stage K (copy hi) ----
        const uint4* Khg = (const uint4*)(g_kh + ((size_t)b * S_ + (size_t)kt * 128) * 64);
        #pragma unroll
        for (int t = 0; t < 4; t++) {
            int idx = tid + t * 512;
            int row = idx >> 4, c4 = idx & 15;
            *(uint4*)&su[U_K + row * AQ_S + c4 * 4] = Khg[idx];
        }
        __syncthreads();

        // ---- S = Qh*Kh ----
        float s[2][4][4];
        #pragma unroll
        for (int mt = 0; mt < 2; mt++)
            #pragma unroll
            for (int nt = 0; nt < 4; nt++)
                #pragma unroll
                for (int i = 0; i < 4; i++) s[mt][nt][i] = 0.f;

        #pragma unroll 1
        for (int c = 0; c < 8; c++) {
            const int co = c * 8;
            uint32_t ah[2][4];
            #pragma unroll
            for (int mt = 0; mt < 2; mt++) {
                int o0 = (wr * 32 + mt * 16 + rowt) * AQ_S + co + colt;
                int o1 = o0 + 8 * AQ_S;
                ah[mt][0] = su[U_Q + o0];      ah[mt][1] = su[U_Q + o1];
                ah[mt][2] = su[U_Q + o0 + 4];  ah[mt][3] = su[U_Q + o1 + 4];
            }
            #pragma unroll
            for (int nt = 0; nt < 4; nt++) {
                int ob = (wc * 32 + nt * 8 + rowt) * AQ_S + co + colt;
                uint32_t bh0 = su[U_K + ob], bh1 = su[U_K + ob + 4];
                #pragma unroll
                for (int mt = 0; mt < 2; mt++)
                    mma_f16(s[mt][nt], ah[mt][0], ah[mt][1], ah[mt][2], ah[mt][3], bh0, bh1);
            }
        }

        // ---- mask + scale; per-warp partial row max ----
        const int* mbase = mask + ((size_t)b * S_ + (size_t)qt * 128) * S_ + (size_t)kt * 128
                                + wc * 32 + colt * 2;
        #pragma unroll
        for (int mt = 0; mt < 2; mt++) {
            int r0 = wr * 32 + mt * 16 + rowt;
            const int* m0p = mbase + (size_t)r0 * S_;
            const int* m1p = mbase + (size_t)(r0 + 8) * S_;
            float mx0 = -1e30f, mx1 = -1e30f;
            #pragma unroll
            for (int nt = 0; nt < 4; nt++) {
                int2 ma = *(const int2*)(m0p + nt * 8);
                int2 mb = *(const int2*)(m1p + nt * 8);
                s[mt][nt][0] = ma.x ? s[mt][nt][0] * scale : -1e9f;
                s[mt][nt][1] = ma.y ? s[mt][nt][1] * scale : -1e9f;
                s[mt][nt][2] = mb.x ? s[mt][nt][2] * scale : -1e9f;
                s[mt][nt][3] = mb.y ? s[mt][nt][3] * scale : -1e9f;
                mx0 = fmaxf(mx0, fmaxf(s[mt][nt][0], s[mt][nt][1]));
                mx1 = fmaxf(mx1, fmaxf(s[mt][nt][2], s[mt][nt][3]));
            }
            mx0 = fmaxf(mx0, __shfl_xor_sync(0xffffffffu, mx0, 1));
            mx0 = fmaxf(mx0, __shfl_xor_sync(0xffffffffu, mx0, 2));
            mx1 = fmaxf(mx1, __shfl_xor_sync(0xffffffffu, mx1, 1));
            mx1 = fmaxf(mx1, __shfl_xor_sync(0xffffffffu, mx1, 2));
            if (colt == 0) {
                redm[r0 * 4 + wc]       = mx0;
                redm[(r0 + 8) * 4 + wc] = mx1;
            }
        }
        __syncthreads();            // K consumed; redm visible

        // ---- stage V: transpose-pack hi (PRMT) ----
        const uint32_t* Vhg = g_vh + ((size_t)b * S_ + (size_t)kt * 128) * 64;
        #pragma unroll
        for (int t = 0; t < 4; t++) {
            int idx = tid + t * 512;               // 0..2047
            int kp = idx >> 5, n4 = idx & 31;
            int ga = (2 * kp) * 64 + n4 * 2;
            int gb = ga + 64;
            uint2 ah2 = *(const uint2*)(Vhg + ga);
            uint2 bh2 = *(const uint2*)(Vhg + gb);
            uint4 oh;
            oh.x = __byte_perm(ah2.x, bh2.x, 0x5410);
            oh.y = __byte_perm(ah2.x, bh2.x, 0x7632);
            oh.z = __byte_perm(ah2.y, bh2.y, 0x5410);
            oh.w = __byte_perm(ah2.y, bh2.y, 0x7632);
            *(uint4*)&su[U_V + kp * AV_S + n4 * 4] = oh;
        }

        // ---- softmax: exp, partial sums, rescale acc, write Ph ----
        float crr[4];
        #pragma unroll
        for (int mt = 0; mt < 2; mt++) {
            int r0 = wr * 32 + mt * 16 + rowt;
            int r1 = r0 + 8;
            float mn0 = fmaxf(fmaxf(redm[r0 * 4], redm[r0 * 4 + 1]),
                              fmaxf(redm[r0 * 4 + 2], redm[r0 * 4 + 3]));
            float mn1 = fmaxf(fmaxf(redm[r1 * 4], redm[r1 * 4 + 1]),
                              fmaxf(redm[r1 * 4 + 2], redm[r1 * 4 + 3]));
            mn0 = fmaxf(mrow[mt*2], mn0);
            mn1 = fmaxf(mrow[mt*2+1], mn1);
            crr[mt*2]   = __expf(mrow[mt*2]   - mn0);
            crr[mt*2+1] = __expf(mrow[mt*2+1] - mn1);
            mrow[mt*2] = mn0;  mrow[mt*2+1] = mn1;
            float sm0 = 0.f, sm1 = 0.f;
            #pragma unroll
            for (int nt = 0; nt < 4; nt++) {
                float p0 = __expf(s[mt][nt][0] - mn0);
                float p1 = __expf(s[mt][nt][1] - mn0);
                float p2 = __expf(s[mt][nt][2] - mn1);
                float p3 = __expf(s[mt][nt][3] - mn1);
                sm0 += p0 + p1;  sm1 += p2 + p3;
                int pc = wc * 16 + nt * 4 + colt;
                su[U_P + r0 * AQ_S + pc] = pack2h(p0, p1);
                su[U_P + r1 * AQ_S + pc] = pack2h(p2, p3);
                acc[mt][nt][0] *= crr[mt*2];   acc[mt][nt][1] *= crr[mt*2];
                acc[mt][nt][2] *= crr[mt*2+1]; acc[mt][nt][3] *= crr[mt*2+1];
            }
            sm0 += __shfl_xor_sync(0xffffffffu, sm0, 1);
            sm0 += __shfl_xor_sync(0xffffffffu, sm0, 2);
            sm1 += __shfl_xor_sync(0xffffffffu, sm1, 1);
            sm1 += __shfl_xor_sync(0xffffffffu, sm1, 2);
            if (colt == 0) {
                reds[r0 * 4 + wc] = sm0;
                reds[r1 * 4 + wc] = sm1;
            }
        }
        __syncthreads();            // P + sum partials + V visible

        // ---- update l ----
        #pragma unroll
        for (int mt = 0; mt < 2; mt++) {
            int r0 = wr * 32 + mt * 16 + rowt;
            int r1 = r0 + 8;
            lrow[mt*2]   = lrow[mt*2]   * crr[mt*2]
                         + reds[r0*4] + reds[r0*4+1] + reds[r0*4+2] + reds[r0*4+3];
            lrow[mt*2+1] = lrow[mt*2+1] * crr[mt*2+1]
                         + reds[r1*4] + reds[r1*4+1] + reds[r1*4+2] + reds[r1*4+3];
        }

        // ---- acc += Ph * Vh ----
        #pragma unroll 1
        for (int c = 0; c < 8; c++) {
            const int co = c * 8;
            uint32_t ah[2][4];
            #pragma unroll
            for (int mt = 0; mt < 2; mt++) {
                int o0 = (wr * 32 + mt * 16 + rowt) * AQ_S + co + colt;
                int o1 = o0 + 8 * AQ_S;
                ah[mt][0] = su[U_P + o0];      ah[mt][1] = su[U_P + o1];
                ah[mt][2] = su[U_P + o0 + 4];  ah[mt][3] = su[U_P + o1 + 4];
            }
            #pragma unroll
            for (int nt = 0; nt < 4; nt++) {
                int ob = (co + colt) * AV_S + wc * 32 + nt * 8 + rowt;
                uint32_t bh0 = su[U_V + ob], bh1 = su[U_V + ob + 4 * AV_S];
                #pragma unroll
                for (int mt = 0; mt < 2; mt++)
                    mma_f16(acc[mt][nt], ah[mt][0], ah[mt][1], ah[mt][2], ah[mt][3], bh0, bh1);
            }
        }
    }

    // ---- epilogue ----
    #pragma unroll
    for (int mt = 0; mt < 2; mt++) {
        int r0 = wr * 32 + mt * 16 + rowt;
        float il0 = 1.f / lrow[mt*2];
        float il1 = 1.f / lrow[mt*2+1];
        size_t gr = (size_t)b * S_ + (size_t)qt * 128 + r0;
        #pragma unroll
        for (int nt = 0; nt < 4; nt++) {
            int c0 = wc * 32 + nt * 8 + colt * 2;
            float2 o0 = { acc[mt][nt][0] * il0, acc[mt][nt][1] * il0 };
            float2 o1 = { acc[mt][nt][2] * il1, acc[mt][nt][3] * il1 };
            *(float2*)(out + gr * DK + c0)       = o0;
            *(float2*)(out + (gr + 8) * DK + c0) = o1;
        }
    }
}

// ===================== launch =====================
extern "C" void kernel_launch(void* const* d_in, const int* in_sizes, int n_in,
                              void* d_out, int out_size)
{
    const float* query = (const float*)d_in[0];
    const float* key   = (const float*)d_in[1];
    const float* value = (const float*)d_in[2];
    const int*   maskp = (const int*)  d_in[3];
    const float* Wq    = (const float*)d_in[4];
    const float* Wk    = (const float*)d_in[5];
    const float* Wv    = (const float*)d_in[6];
    float* out = (float*)d_out;

    cudaFuncSetAttribute(proj_mma, cudaFuncAttributeMaxDynamicSharedMemorySize,
                         (int)PJ_SMEM_BYTES);
    cudaFuncSetAttribute(attn_tc, cudaFuncAttributeMaxDynamicSharedMemorySize,
                         (int)A_SMEM_BYTES);

    presplit_w<<<768, 256>>>(Wq, Wk, Wv);
    proj_mma<<<dim3(NROWS / 128, 3), 512, PJ_SMEM_BYTES>>>(query, key, value);
    attn_tc<<<dim3(S_ / 128, B_), 512, A_SMEM_BYTES>>>(maskp, out);
}